// round 13
// baseline (speedup 1.0000x reference)
#include <cuda_runtime.h>
#include <math.h>

// LSTM autoregressive decoder, B=256, H=1024, I=1, O=512, T=512.
// Single persistent kernel, software grid barriers (2/step).
// fp32 via packed fma.rn.f32x2 (FFMA2) over the k dimension.
// Thread tile phase A: 2j x 4gates x 4b  -> 4 LDS.128 per warp per 4k.

#define BATCH  256
#define HID    1024
#define OUTF   512
#define TSTEPS 512
#define NBLK   128
#define NTHR   256

__device__ __align__(16) float g_h[2][BATCH * HID];
__device__ unsigned long long g_part[BATCH][16];   // packed argmax partials per o-tile
__device__ int g_count;
__device__ unsigned g_sense;

__device__ __forceinline__ void gridbar(unsigned sense_val) {
    __threadfence();
    __syncthreads();
    if (threadIdx.x == 0) {
        if (atomicAdd(&g_count, 1) == NBLK - 1) {
            atomicExch(&g_count, 0);
            __threadfence();
            atomicExch(&g_sense, sense_val ^ 1);
        } else {
            while (*(volatile unsigned*)&g_sense == sense_val) __nanosleep(32);
        }
    }
    __syncthreads();
}

__device__ __forceinline__ float sigf(float x) { return 1.f / (1.f + expf(-x)); }

__device__ __forceinline__ unsigned long long fma2(unsigned long long a,
                                                   unsigned long long b,
                                                   unsigned long long c) {
    unsigned long long d;
    asm("fma.rn.f32x2 %0, %1, %2, %3;" : "=l"(d) : "l"(a), "l"(b), "l"(c));
    return d;
}
__device__ __forceinline__ float lo32(unsigned long long a) {
    return __uint_as_float((unsigned)a);
}
__device__ __forceinline__ float hi32(unsigned long long a) {
    return __uint_as_float((unsigned)(a >> 32));
}

__global__ __launch_bounds__(NTHR, 1)
void lstm_persistent(const float* __restrict__ z,
                     const float* __restrict__ w_ih,
                     const float* __restrict__ w_hh,
                     const float* __restrict__ b_ih,
                     const float* __restrict__ b_hh,
                     const float* __restrict__ w_lin,
                     const float* __restrict__ b_lin,
                     float* __restrict__ out)
{
    // 16 KB staging pool, layout [kkg 0..31][b 0..31][kl 0..3] (words).
    __shared__ __align__(16) float pool[4096];
    __shared__ float xin_s[32];

    const int blk = blockIdx.x;
    const int t   = threadIdx.x;

    // ----- Phase A identity: 16 j-tiles(64) x 8 b-tiles(32) -----
    const int jt  = blk & 15;
    const int btA = blk >> 4;
    const int bg  = t & 7;          // 8 batch groups; b = bg + 8i
    const int jl  = t >> 3;         // 0..31; thread j's: jl and jl+32

    const float* wA[4][2];
    float biasA[4][2], wihA[4][2];
#pragma unroll
    for (int g = 0; g < 4; g++)
#pragma unroll
        for (int jj = 0; jj < 2; jj++) {
            int row = (g << 10) + (jt << 6) + jl + (jj << 5);
            wA[g][jj]   = w_hh + (size_t)row * HID;
            biasA[g][jj] = b_ih[row] + b_hh[row];
            wihA[g][jj]  = w_ih[row];
        }

    // ----- Phase B identity: 16 o-tiles(32) x 8 b-tiles(32) -----
    const int otB = blk & 15;
    const int btB = blk >> 4;
    const int og  = t & 7;          // o = otB*32 + oo*8 + og
    const int bB  = t >> 3;         // 0..31
    const int bGB = (btB << 5) + bB;

    const float* wB[4];
    float blv[4];
    int oIdx[4];
#pragma unroll
    for (int oo = 0; oo < 4; oo++) {
        int o = (otB << 5) + (oo << 3) + og;
        oIdx[oo] = o;
        wB[oo]  = w_lin + (size_t)o * HID;
        blv[oo] = b_lin[o];
    }

    float c_reg[2][4];
#pragma unroll
    for (int jj = 0; jj < 2; jj++)
#pragma unroll
        for (int i = 0; i < 4; i++) c_reg[jj][i] = 0.f;

    unsigned sense = *(volatile unsigned*)&g_sense;

    for (int s = 0; s < TSTEPS; s++) {
        const float* __restrict__ hin = (s == 0) ? z : g_h[(s + 1) & 1];
        float* __restrict__ hout = g_h[s & 1];

        // xin for this block's 32 batch rows from previous step's partials
        if (t < 32) {
            float x = 0.f;
            if (s > 0) {
                const unsigned long long* p = g_part[(btA << 5) + t];
                unsigned long long k = __ldcg(&p[0]);
#pragma unroll
                for (int q = 1; q < 16; q++) {
                    unsigned long long kq = __ldcg(&p[q]);
                    if (kq > k) k = kq;
                }
                x = (float)(0xFFFFFFFFu - (unsigned)(k & 0xFFFFFFFFull));
            }
            xin_s[t] = x;
        }

        // ---------------- Phase A: gates GEMM (f32x2) ----------------
        unsigned long long acc[4][2][4];
#pragma unroll
        for (int g = 0; g < 4; g++)
#pragma unroll
            for (int jj = 0; jj < 2; jj++)
#pragma unroll
                for (int i = 0; i < 4; i++) acc[g][jj][i] = 0ull;

        for (int kc = 0; kc < HID; kc += 128) {
            __syncthreads();
            // stage 32b x 128k into [kkg][b*4] layout
#pragma unroll
            for (int r = 0; r < 4; r++) {
                int idx = r * 256 + t;
                int bb = idx & 31, kkg = idx >> 5;
                *(float4*)&pool[(kkg << 7) + (bb << 2)] =
                    __ldcg((const float4*)(hin + (size_t)((btA << 5) + bb) * HID + kc + (kkg << 2)));
            }
            __syncthreads();

#pragma unroll 4
            for (int kkg = 0; kkg < 32; kkg++) {
                ulonglong2 hv[4];
#pragma unroll
                for (int i = 0; i < 4; i++)
                    hv[i] = *(const ulonglong2*)&pool[(kkg << 7) + ((bg + (i << 3)) << 2)];
#pragma unroll
                for (int g = 0; g < 4; g++)
#pragma unroll
                    for (int jj = 0; jj < 2; jj++) {
                        ulonglong2 wv = *(const ulonglong2*)(wA[g][jj] + kc + (kkg << 2));
#pragma unroll
                        for (int i = 0; i < 4; i++) {
                            acc[g][jj][i] = fma2(wv.x, hv[i].x, acc[g][jj][i]);
                            acc[g][jj][i] = fma2(wv.y, hv[i].y, acc[g][jj][i]);
                        }
                    }
            }
        }

        // ---------------- Cell update (gates fused per thread) ----------------
#pragma unroll
        for (int jj = 0; jj < 2; jj++)
#pragma unroll
            for (int i = 0; i < 4; i++) {
                float xv = xin_s[bg + (i << 3)];
                float pre[4];
#pragma unroll
                for (int g = 0; g < 4; g++) {
                    unsigned long long a = acc[g][jj][i];
                    pre[g] = lo32(a) + hi32(a) + biasA[g][jj] + xv * wihA[g][jj];
                }
                float cn = sigf(pre[1]) * c_reg[jj][i] + sigf(pre[0]) * tanhf(pre[2]);
                float hn = sigf(pre[3]) * tanhf(cn);
                c_reg[jj][i] = cn;
                int b = (btA << 5) + bg + (i << 3);
                hout[(size_t)b * HID + (jt << 6) + jl + (jj << 5)] = hn;
            }

        gridbar(sense); sense ^= 1;   // h_new visible everywhere

        // ---------------- Phase B: head GEMM + logits + argmax ----------------
        unsigned long long acc2[4] = {0ull, 0ull, 0ull, 0ull};

        for (int kc = 0; kc < HID; kc += 128) {
            __syncthreads();
#pragma unroll
            for (int r = 0; r < 4; r++) {
                int idx = r * 256 + t;
                int bb = idx & 31, kkg = idx >> 5;
                *(float4*)&pool[(kkg << 7) + (bb << 2)] =
                    __ldcg((const float4*)(hout + (size_t)((btB << 5) + bb) * HID + kc + (kkg << 2)));
            }
            __syncthreads();

#pragma unroll 4
            for (int kkg = 0; kkg < 32; kkg++) {
                ulonglong2 hv = *(const ulonglong2*)&pool[(kkg << 7) + (bB << 2)];
#pragma unroll
                for (int oo = 0; oo < 4; oo++) {
                    ulonglong2 wv = *(const ulonglong2*)(wB[oo] + kc + (kkg << 2));
                    acc2[oo] = fma2(wv.x, hv.x, acc2[oo]);
                    acc2[oo] = fma2(wv.y, hv.y, acc2[oo]);
                }
            }
        }

        {
            size_t obase = (size_t)bGB * (TSTEPS * OUTF) + (size_t)s * OUTF;
            unsigned long long best = 0ull;
#pragma unroll
            for (int oo = 0; oo < 4; oo++) {
                float v = lo32(acc2[oo]) + hi32(acc2[oo]) + blv[oo];
                out[obase + oIdx[oo]] = v;
                unsigned u = __float_as_uint(v);
                u = (u & 0x80000000u) ? ~u : (u | 0x80000000u);   // order-preserving
                unsigned long long key = ((unsigned long long)u << 32)
                                       | (unsigned long long)(0xFFFFFFFFu - (unsigned)oIdx[oo]);
                if (key > best) best = key;
            }
            // reduce across the 8 og lanes of this b (lanes differ only in low 3 bits)
#pragma unroll
            for (int off = 1; off < 8; off <<= 1) {
                unsigned long long ok = __shfl_xor_sync(0xffffffffu, best, off);
                if (ok > best) best = ok;
            }
            if (og == 0) g_part[bGB][otB] = best;
        }

        gridbar(sense); sense ^= 1;   // argmax partials visible
    }
}

extern "C" void kernel_launch(void* const* d_in, const int* in_sizes, int n_in,
                              void* d_out, int out_size)
{
    (void)in_sizes; (void)n_in; (void)out_size;
    const float* z     = (const float*)d_in[0];
    const float* w_ih  = (const float*)d_in[1];
    const float* w_hh  = (const float*)d_in[2];
    const float* b_ih  = (const float*)d_in[3];
    const float* b_hh  = (const float*)d_in[4];
    const float* w_lin = (const float*)d_in[5];
    const float* b_lin = (const float*)d_in[6];
    float* out = (float*)d_out;

    lstm_persistent<<<NBLK, NTHR>>>(z, w_ih, w_hh, b_ih, b_hh, w_lin, b_lin, out);
}

// round 15
// speedup vs baseline: 1.2025x; 1.2025x over previous
#include <cuda_runtime.h>
#include <math.h>

// LSTM decoder B=256,H=1024,I=1,O=512,T=512. Persistent kernel, 1 graph node.
// All weights SM-resident in dynamic smem for all 512 steps.

#define HID    1024
#define OUTF   512
#define TSTEPS 512
#define NBLK   128
#define NTHR   256
#define WP     1028            // weight row pitch (floats)
#define HP     9               // h staging pitch (float2)
#define CHUNK  16
#define NCH    (HID / CHUNK)

__device__ __align__(16) float g_h[2][256 * HID];
__device__ unsigned long long g_best[2][256];
__device__ int g_count;
__device__ unsigned g_sense;

#define F_WS   0
#define F_WLS  (F_WS + 32 * WP)
#define F_H    (F_WLS + 4 * WP)             // 2 bufs * 2304 float2 = 9216 floats
#define F_XIN  (F_H + 9216)
#define F_BW   (F_XIN + 256)
#define SMEM_FLOATS (F_BW + 64)

__device__ __forceinline__ void gridbar(unsigned sv) {
    __threadfence();
    __syncthreads();
    if (threadIdx.x == 0) {
        if (atomicAdd(&g_count, 1) == NBLK - 1) {
            atomicExch(&g_count, 0);
            __threadfence();
            atomicExch(&g_sense, sv ^ 1);
        } else {
            while (*(volatile unsigned*)&g_sense == sv) __nanosleep(32);
        }
    }
    __syncthreads();
}

__device__ __forceinline__ float sigf(float x) { return 1.f / (1.f + expf(-x)); }

__device__ __forceinline__ unsigned long long fma2(unsigned long long a,
                                                   unsigned long long b,
                                                   unsigned long long c) {
    unsigned long long d;
    asm("fma.rn.f32x2 %0, %1, %2, %3;" : "=l"(d) : "l"(a), "l"(b), "l"(c));
    return d;
}
__device__ __forceinline__ float lo32(unsigned long long a) { return __uint_as_float((unsigned)a); }
__device__ __forceinline__ float hi32(unsigned long long a) { return __uint_as_float((unsigned)(a >> 32)); }

__device__ __forceinline__ void stage8(float2* hb, unsigned ft,
                                       float4 a, float4 b, float4 c, float4 d) {
    hb[0u ^ ft] = make_float2(a.x, a.y);
    hb[1u ^ ft] = make_float2(a.z, a.w);
    hb[2u ^ ft] = make_float2(b.x, b.y);
    hb[3u ^ ft] = make_float2(b.z, b.w);
    hb[4u ^ ft] = make_float2(c.x, c.y);
    hb[5u ^ ft] = make_float2(c.z, c.w);
    hb[6u ^ ft] = make_float2(d.x, d.y);
    hb[7u ^ ft] = make_float2(d.z, d.w);
}

__global__ __launch_bounds__(NTHR, 1)
void lstm_persistent(const float* __restrict__ z,
                     const float* __restrict__ w_ih,
                     const float* __restrict__ w_hh,
                     const float* __restrict__ b_ih,
                     const float* __restrict__ b_hh,
                     const float* __restrict__ w_lin,
                     const float* __restrict__ b_lin,
                     float* __restrict__ out)
{
    extern __shared__ float sm[];
    float*  w_s   = sm + F_WS;
    float*  wl_s  = sm + F_WLS;
    float2* h_s   = (float2*)(sm + F_H);     // [buf][256 b][HP]
    float*  xin_s = sm + F_XIN;
    float*  bw_s  = sm + F_BW;               // [0..31] bias, [32..63] w_ih

    const int blk = blockIdx.x;
    const int t   = threadIdx.x;
    const int rg  = t & 3;                          // row group 0..3
    const int bg  = t >> 2;                         // batch group 0..63 (b = 4bg+sl)
    const unsigned fbg = (unsigned)(bg & 7);        // swizzle for b=4bg+sl
    const unsigned ft  = (unsigned)((t >> 2) & 7);  // swizzle for b=t

    // ---- load resident weights once ----
    // slot rp -> (g = (rp>>2)&3, jl = 2*(rp&3) + (rp>>4));  j = blk*8 + jl
    for (int rp = 0; rp < 32; rp++) {
        int g  = (rp >> 2) & 3;
        int jl = 2 * (rp & 3) + (rp >> 4);
        const float* src = w_hh + (size_t)((g << 10) + (blk << 3) + jl) * HID;
        *(float4*)(w_s + rp * WP + t * 4) = *(const float4*)(src + t * 4);
    }
#pragma unroll
    for (int oo = 0; oo < 4; oo++) {
        const float* src = w_lin + (size_t)((blk << 2) + oo) * HID;
        *(float4*)(wl_s + oo * WP + t * 4) = *(const float4*)(src + t * 4);
    }
    if (t < 32) {
        int g  = (t >> 2) & 3;
        int jl = 2 * (t & 3) + (t >> 4);
        int row = (g << 10) + (blk << 3) + jl;
        bw_s[t]      = b_ih[row] + b_hh[row];
        bw_s[32 + t] = w_ih[row];
    }
    float blB[4];
#pragma unroll
    for (int oo = 0; oo < 4; oo++) blB[oo] = b_lin[(blk << 2) + oo];
    __syncthreads();

    float c_reg[2][4];
#pragma unroll
    for (int j = 0; j < 2; j++)
#pragma unroll
        for (int sl = 0; sl < 4; sl++) c_reg[j][sl] = 0.f;

    unsigned sense = *(volatile unsigned*)&g_sense;

    for (int s = 0; s < TSTEPS; s++) {
        const float* __restrict__ hin = (s == 0) ? z : g_h[(s + 1) & 1];
        float* __restrict__ hout = g_h[s & 1];

        // xin (from last step's argmax) + reset this step's argmax buffer
        {
            float x = 0.f;
            if (s > 0) {
                unsigned long long k = __ldcg(&g_best[(s + 1) & 1][t]);
                x = (float)(0xFFFFFFFFu - (unsigned)(k & 0xFFFFFFFFull));
            }
            xin_s[t] = x;
            if (t < 2) g_best[s & 1][(blk << 1) + t] = 0ull;
        }

        // ============ Phase A: gates GEMM (w smem-resident) ============
        unsigned long long acc[8][4];
#pragma unroll
        for (int i = 0; i < 8; i++)
#pragma unroll
            for (int sl = 0; sl < 4; sl++) acc[i][sl] = 0ull;

        float4 s0, s1, s2, s3;
        {
            const float* p = hin + (size_t)t * HID;
            s0 = __ldcg((const float4*)(p + 0));
            s1 = __ldcg((const float4*)(p + 4));
            s2 = __ldcg((const float4*)(p + 8));
            s3 = __ldcg((const float4*)(p + 12));
            stage8(h_s + t * HP, ft, s0, s1, s2, s3);
            __syncthreads();
        }
        int buf = 0;
        for (int c = 0; c < NCH; c++) {
            if (c + 1 < NCH) {
                const float* p = hin + (size_t)t * HID + (c + 1) * CHUNK;
                s0 = __ldcg((const float4*)(p + 0));
                s1 = __ldcg((const float4*)(p + 4));
                s2 = __ldcg((const float4*)(p + 8));
                s3 = __ldcg((const float4*)(p + 12));
            }
            const float2* hbase = h_s + buf * 2304;
#pragma unroll
            for (int q = 0; q < 4; q++) {
                const int kabs = c * CHUNK + q * 4;
                const unsigned p0 = (unsigned)(q * 2);
                ulonglong2 wv[8];
#pragma unroll
                for (int i = 0; i < 8; i++)
                    wv[i] = *(const ulonglong2*)(w_s + (4 * i + rg) * WP + kabs);
                unsigned long long h0[4], h1[4];
#pragma unroll
                for (int sl = 0; sl < 4; sl++) {
                    const float2* hb = hbase + (4 * bg + sl) * HP;
                    h0[sl] = *(const unsigned long long*)&hb[p0 ^ fbg];
                    h1[sl] = *(const unsigned long long*)&hb[(p0 + 1u) ^ fbg];
                }
#pragma unroll
                for (int i = 0; i < 8; i++)
#pragma unroll
                    for (int sl = 0; sl < 4; sl++) {
                        acc[i][sl] = fma2(wv[i].x, h0[sl], acc[i][sl]);
                        acc[i][sl] = fma2(wv[i].y, h1[sl], acc[i][sl]);
                    }
            }
            __syncthreads();
            if (c + 1 < NCH) {
                stage8(h_s + (buf ^ 1) * 2304 + t * HP, ft, s0, s1, s2, s3);
                __syncthreads();
            }
            buf ^= 1;
        }

        // cell update: i -> (g = i&3, jlh = i>>2), jl = 2*rg + jlh
#pragma unroll
        for (int sl = 0; sl < 4; sl++) {
            const int b = 4 * bg + sl;
            const float xv = xin_s[b];
            float hn2[2];
#pragma unroll
            for (int jlh = 0; jlh < 2; jlh++) {
                float pre[4];
#pragma unroll
                for (int g = 0; g < 4; g++) {
                    const int i  = 4 * jlh + g;
                    const int rp = 4 * i + rg;
                    unsigned long long a = acc[i][sl];
                    pre[g] = lo32(a) + hi32(a) + bw_s[rp] + xv * bw_s[32 + rp];
                }
                float cn = sigf(pre[1]) * c_reg[jlh][sl] + sigf(pre[0]) * tanhf(pre[2]);
                c_reg[jlh][sl] = cn;
                hn2[jlh] = sigf(pre[3]) * tanhf(cn);
            }
            *(float2*)(hout + (size_t)b * HID + (blk << 3) + 2 * rg) =
                make_float2(hn2[0], hn2[1]);
        }

        gridbar(sense); sense ^= 1;   // h_new + g_best resets visible

        // ============ Phase B: head GEMM + logits + argmax ============
        unsigned long long accB[4] = {0ull, 0ull, 0ull, 0ull};
        {
            const float* p = hout + (size_t)t * HID;
            s0 = __ldcg((const float4*)(p + 0));
            s1 = __ldcg((const float4*)(p + 4));
            s2 = __ldcg((const float4*)(p + 8));
            s3 = __ldcg((const float4*)(p + 12));
            stage8(h_s + t * HP, ft, s0, s1, s2, s3);
            __syncthreads();
        }
        buf = 0;
        for (int c = 0; c < NCH; c++) {
            if (c + 1 < NCH) {
                const float* p = hout + (size_t)t * HID + (c + 1) * CHUNK;
                s0 = __ldcg((const float4*)(p + 0));
                s1 = __ldcg((const float4*)(p + 4));
                s2 = __ldcg((const float4*)(p + 8));
                s3 = __ldcg((const float4*)(p + 12));
            }
            const float2* hb = h_s + buf * 2304 + t * HP;
#pragma unroll
            for (int q = 0; q < 4; q++) {
                const int kabs = c * CHUNK + q * 4;
                const unsigned p0 = (unsigned)(q * 2);
                unsigned long long h0 = *(const unsigned long long*)&hb[p0 ^ ft];
                unsigned long long h1 = *(const unsigned long long*)&hb[(p0 + 1u) ^ ft];
#pragma unroll
                for (int oo = 0; oo < 4; oo++) {
                    ulonglong2 wv = *(const ulonglong2*)(wl_s + oo * WP + kabs);
                    accB[oo] = fma2(wv.x, h0, accB[oo]);
                    accB[oo] = fma2(wv.y, h1, accB[oo]);
                }
            }
            __syncthreads();
            if (c + 1 < NCH) {
                stage8(h_s + (buf ^ 1) * 2304 + t * HP, ft, s0, s1, s2, s3);
                __syncthreads();
            }
            buf ^= 1;
        }

        {
            float v[4];
            unsigned long long best = 0ull;
#pragma unroll
            for (int oo = 0; oo < 4; oo++) {
                v[oo] = lo32(accB[oo]) + hi32(accB[oo]) + blB[oo];
                unsigned u = __float_as_uint(v[oo]);
                u = (u & 0x80000000u) ? ~u : (u | 0x80000000u);  // order-preserving
                unsigned o = (unsigned)((blk << 2) + oo);
                unsigned long long key = ((unsigned long long)u << 32)
                                       | (unsigned long long)(0xFFFFFFFFu - o);
                if (key > best) best = key;
            }
            *(float4*)(out + (size_t)t * (TSTEPS * OUTF) + (size_t)s * OUTF + (blk << 2)) =
                make_float4(v[0], v[1], v[2], v[3]);
            atomicMax(&g_best[s & 1][t], best);
        }

        gridbar(sense); sense ^= 1;   // argmax visible
    }
}

extern "C" void kernel_launch(void* const* d_in, const int* in_sizes, int n_in,
                              void* d_out, int out_size)
{
    (void)in_sizes; (void)n_in; (void)out_size;
    const float* z     = (const float*)d_in[0];
    const float* w_ih  = (const float*)d_in[1];
    const float* w_hh  = (const float*)d_in[2];
    const float* b_ih  = (const float*)d_in[3];
    const float* b_hh  = (const float*)d_in[4];
    const float* w_lin = (const float*)d_in[5];
    const float* b_lin = (const float*)d_in[6];
    float* out = (float*)d_out;

    static_assert(SMEM_FLOATS * 4 <= 227 * 1024, "smem budget");
    cudaFuncSetAttribute(lstm_persistent,
                         cudaFuncAttributeMaxDynamicSharedMemorySize,
                         SMEM_FLOATS * 4);
    lstm_persistent<<<NBLK, NTHR, SMEM_FLOATS * 4>>>(
        z, w_ih, w_hh, b_ih, b_hh, w_lin, b_lin, out);
}